// round 15
// baseline (speedup 1.0000x reference)
#include <cuda_runtime.h>
#include <cuda_bf16.h>
#include <stdint.h>

#define NTOK   16384
#define DIM    256
#define NCODES 8192

// Device-global scratch (device-code references ONLY — GB300 ATS trap:
// passing __device__ symbols as host-side kernel args reads host memory).
__device__ unsigned long long g_key[NTOK];
__device__ float  g_rown[NTOK];
__device__ float  g_coden[NCODES];
__device__ double g_partial[1024];
__device__ float  g_xTd[DIM * 2 * NTOK];   // x transposed + duplicated: [d][2*tok]
__device__ float  g_cT[DIM * NCODES];      // cb transposed: [d][code]

// ---------------------------------------------------------------------------
__device__ __forceinline__ uint32_t smem_u32(const void* p) {
    uint32_t a;
    asm("{ .reg .u64 t; cvta.to.shared.u64 t, %1; cvt.u32.u64 %0, t; }" : "=r"(a) : "l"(p));
    return a;
}
__device__ __forceinline__ void unpackf2(unsigned long long v, float& lo, float& hi) {
    asm("mov.b64 {%0, %1}, %2;" : "=f"(lo), "=f"(hi) : "l"(v));
}
// Packed dual fp32 FMA: c.lo += a.lo*b.lo; c.hi += a.hi*b.hi (each IEEE fp32).
__device__ __forceinline__ void fma2(unsigned long long& c, unsigned long long a,
                                     unsigned long long b) {
    asm("fma.rn.f32x2 %0, %1, %2, %0;" : "+l"(c) : "l"(a), "l"(b));
}
#define CPA(dst, src) \
    asm volatile("cp.async.cg.shared.global [%0], [%1], 16;" :: "r"(dst), "l"(src))
#define CPA_COMMIT() asm volatile("cp.async.commit_group;" ::: "memory")
#define CPA_WAIT0()  asm volatile("cp.async.wait_group 0;" ::: "memory")

// ---------------------------------------------------------------------------
// 32x32 tiled transpose. mode 0: x -> g_xTd (duplicated pairs, float2 stores).
// mode 1: cb -> g_cT (straight).
__global__ void k_tr(const float* __restrict__ src, int mode) {
    __shared__ float t[32][33];
    const int tx = threadIdx.x & 31, ty = threadIdx.x >> 5;   // 256 thr
    const int bx = blockIdx.x * 32;   // row (token/code) base
    const int by = blockIdx.y * 32;   // d base
#pragma unroll
    for (int i = ty; i < 32; i += 8)
        t[i][tx] = src[(size_t)(bx + i) * DIM + by + tx];
    __syncthreads();
    if (mode == 0) {
        float2* dst = reinterpret_cast<float2*>(g_xTd);
#pragma unroll
        for (int i = ty; i < 32; i += 8) {
            float v = t[tx][i];
            dst[(size_t)(by + i) * NTOK + bx + tx] = make_float2(v, v);
        }
    } else {
#pragma unroll
        for (int i = ty; i < 32; i += 8)
            g_cT[(size_t)(by + i) * NCODES + bx + tx] = t[tx][i];
    }
}

__global__ void k_init(void) {
    int n = blockIdx.x * 256 + threadIdx.x;
    if (n < NTOK) g_key[n] = ~0ull;
}

__global__ void k_norm(const float* __restrict__ src, int nrows, int which) {
    int gwarp = (blockIdx.x * blockDim.x + threadIdx.x) >> 5;
    int lane  = threadIdx.x & 31;
    if (gwarp >= nrows) return;
    const float4* s4 = reinterpret_cast<const float4*>(src) + (size_t)gwarp * 64;
    float a = 0.0f;
#pragma unroll
    for (int it = 0; it < 2; it++) {
        float4 v = s4[it * 32 + lane];
        a = __fadd_rn(a, __fmul_rn(v.x, v.x));
        a = __fadd_rn(a, __fmul_rn(v.y, v.y));
        a = __fadd_rn(a, __fmul_rn(v.z, v.z));
        a = __fadd_rn(a, __fmul_rn(v.w, v.w));
    }
#pragma unroll
    for (int off = 16; off >= 1; off >>= 1)
        a += __shfl_xor_sync(0xffffffffu, a, off);
    if (lane == 0) { if (which == 0) g_rown[gwarp] = a; else g_coden[gwarp] = a; }
}

// ---------------------------------------------------------------------------
// Fused exact-fp32 GEMM + argmin with packed FFMA2, issue-lean form.
// CTA = 128 rows x 256 codes; thread = 8 rows x 8 code-pairs (8x16 outputs).
// x comes pre-duplicated ((x_r,x_r) via one LDS.64); e pairs are natural.
// Each output dot is a single ascending-d fp32 FMA chain in one f32x2 lane —
// bit-identical to scalar FFMA. dist = fsub(fadd(r,c), 2t);
// key = (dist_bits<<32)|k reproduces jnp.argmin's first-index tie-break.
__global__ void __launch_bounds__(256) k_main() {
    extern __shared__ float sm[];    // x: 2 bufs x 8192 f | e: 2 bufs x 8192 f (128KB)
    const int tid = threadIdx.x;
    const int tx  = tid & 15;        // code-pair selector
    const int ty  = tid >> 4;        // row selector
    const int rowbase = blockIdx.x * 128;
    const int kbase   = blockIdx.y * 256;
    const uint32_t smb = smem_u32(sm);

    unsigned long long acc[8][8];
#pragma unroll
    for (int P = 0; P < 8; P++)
#pragma unroll
        for (int Q = 0; Q < 8; Q++) acc[P][Q] = 0ull;

    const int dl = tid >> 3;         // 0..31: d within chunk
    const int gl = tid & 7;          // granule phase
#define FILL(ct, b)                                                                  \
    do {                                                                             \
        const float* xsrc = &g_xTd[(size_t)((ct) * 32 + dl) * (2 * NTOK) + 2 * rowbase]; \
        const float* esrc = &g_cT[(size_t)((ct) * 32 + dl) * NCODES + kbase];        \
        uint32_t xd = smb + ((b) * 8192 + dl * 256) * 4;                             \
        uint32_t ed = smb + (16384 + (b) * 8192 + dl * 256) * 4;                     \
        _Pragma("unroll")                                                            \
        for (int it = 0; it < 8; it++) {                                             \
            int g = gl + it * 8;                                                     \
            CPA(xd + g * 16, xsrc + g * 4);                                          \
            CPA(ed + g * 16, esrc + g * 4);                                          \
        }                                                                            \
    } while (0)

    FILL(0, 0);
    CPA_COMMIT();
    CPA_WAIT0();
    __syncthreads();

#pragma unroll 1
    for (int ct = 0; ct < 8; ct++) {
        if (ct < 7) { FILL(ct + 1, (ct + 1) & 1); CPA_COMMIT(); }
        const float* xs = sm + (ct & 1) * 8192;
        const float* es = sm + 16384 + (ct & 1) * 8192;
#pragma unroll 2
        for (int d = 0; d < 32; d++) {
            unsigned long long xa[8], eb[8];
#pragma unroll
            for (int P = 0; P < 8; P++)
                xa[P] = *reinterpret_cast<const unsigned long long*>(
                            &xs[d * 256 + (ty + 16 * P) * 2]);
#pragma unroll
            for (int Q = 0; Q < 8; Q++)
                eb[Q] = *reinterpret_cast<const unsigned long long*>(
                            &es[d * 256 + (tx + 16 * Q) * 2]);
#pragma unroll
            for (int P = 0; P < 8; P++)
#pragma unroll
                for (int Q = 0; Q < 8; Q++)
                    fma2(acc[P][Q], xa[P], eb[Q]);
        }
        if (ct < 7) { CPA_WAIT0(); __syncthreads(); }
    }

    // Epilogue: distances + lexicographic argmin.
    float rr[8];
#pragma unroll
    for (int P = 0; P < 8; P++) rr[P] = g_rown[rowbase + ty + 16 * P];
    unsigned long long bk[8];
#pragma unroll
    for (int P = 0; P < 8; P++) bk[P] = ~0ull;

#pragma unroll
    for (int Q = 0; Q < 8; Q++) {
        int k0 = kbase + 2 * (tx + 16 * Q);
        float cn0 = g_coden[k0], cn1 = g_coden[k0 + 1];
#pragma unroll
        for (int P = 0; P < 8; P++) {
            float tlo, thi;
            unpackf2(acc[P][Q], tlo, thi);
            float d0 = __fsub_rn(__fadd_rn(rr[P], cn0), 2.0f * tlo);
            float d1 = __fsub_rn(__fadd_rn(rr[P], cn1), 2.0f * thi);
            unsigned long long q;
            q = ((unsigned long long)__float_as_uint(d0) << 32) | (unsigned)k0;
            if (q < bk[P]) bk[P] = q;
            q = ((unsigned long long)__float_as_uint(d1) << 32) | (unsigned)(k0 + 1);
            if (q < bk[P]) bk[P] = q;
        }
    }
    // reduce across the 16 tx lanes sharing this ty (lane = (ty&1)*16+tx)
#pragma unroll
    for (int P = 0; P < 8; P++) {
        unsigned long long k = bk[P];
#pragma unroll
        for (int off = 8; off >= 1; off >>= 1) {
            unsigned long long o = __shfl_xor_sync(0xffffffffu, k, off);
            if (o < k) k = o;
        }
        if (tx == 0) atomicMin(&g_key[rowbase + ty + 16 * P], k);
    }
}

// ---------------------------------------------------------------------------
__global__ void k_gather(const float* __restrict__ x, const float* __restrict__ cb,
                         float* __restrict__ out, int out_size) {
    double ls = 0.0;
    const int total = NTOK * DIM;
    for (int e = blockIdx.x * 256 + threadIdx.x; e < total; e += 1024 * 256) {
        int n = e >> 8, d = e & 255;
        int idx = (int)(unsigned)(g_key[n] & 0xffffffffull);
        float q  = __ldg(&cb[idx * DIM + d]);
        float xv = x[e];
        float diff = __fsub_rn(q, xv);
        if (e < out_size) out[e] = __fadd_rn(xv, diff);
        ls += (double)__fmul_rn(diff, diff);
    }
#pragma unroll
    for (int off = 16; off >= 1; off >>= 1)
        ls += __shfl_xor_sync(0xffffffffu, ls, off);
    __shared__ double ws[8];
    if ((threadIdx.x & 31) == 0) ws[threadIdx.x >> 5] = ls;
    __syncthreads();
    if (threadIdx.x == 0) {
        double t = 0.0;
        for (int w = 0; w < 8; w++) t += ws[w];
        g_partial[blockIdx.x] = t;
    }
}

__global__ void k_finalize(float* __restrict__ out, int out_size) {
    if (blockIdx.x < 64) {
        int n = blockIdx.x * 256 + threadIdx.x;
        int pos = NTOK * DIM + n;
        if (pos < out_size)
            out[pos] = (float)(unsigned)(g_key[n] & 0xffffffffull);
    } else if (threadIdx.x == 0) {
        double s = 0.0;
        for (int b = 0; b < 1024; b++) s += g_partial[b];
        int pos = NTOK * DIM + NTOK;
        if (pos < out_size)
            out[pos] = 0.25f * (float)(s / (double)(NTOK * DIM));
    }
}

// ---------------------------------------------------------------------------
extern "C" void kernel_launch(void* const* d_in, const int* in_sizes, int n_in,
                              void* d_out, int out_size) {
    const float* x  = (const float*)d_in[0];
    const float* cb = (const float*)d_in[1];
    if (n_in >= 2 && in_sizes[0] == NCODES * DIM) {
        cb = (const float*)d_in[0];
        x  = (const float*)d_in[1];
    }
    float* out = (float*)d_out;

    cudaFuncSetAttribute(k_main, cudaFuncAttributeMaxDynamicSharedMemorySize, 131072);

    k_tr<<<dim3(NTOK / 32, DIM / 32), 256>>>(x, 0);
    k_tr<<<dim3(NCODES / 32, DIM / 32), 256>>>(cb, 1);
    k_init<<<(NTOK + 255) / 256, 256>>>();
    k_norm<<<NTOK / 8, 256>>>(x, NTOK, 0);
    k_norm<<<NCODES / 8, 256>>>(cb, NCODES, 1);
    k_main<<<dim3(NTOK / 128, NCODES / 256), 256, 131072>>>();
    k_gather<<<1024, 256>>>(x, cb, out, out_size);
    k_finalize<<<65, 256>>>(out, out_size);
}